// round 11
// baseline (speedup 1.0000x reference)
#include <cuda_runtime.h>
#include <cuda_bf16.h>
#include <cuda_fp16.h>
#include <math.h>
#include <stdint.h>

// Problem constants
#define NM 1024
#define NH 16
#define ND 64
#define BATCH 4
#define SEQ 1024
#define ROWS (BATCH*SEQ)   // 4096

// ---------------------------------------------------------------------------
// Scratch (device globals; no allocation allowed)
// ---------------------------------------------------------------------------
__device__ __half g_x[ROWS * NM];
__device__ __half g_w[4][NM * NM];
__device__ __half g_q[ROWS * NM];
__device__ __half g_k[ROWS * NM];
__device__ __half g_v[ROWS * NM];
__device__ __half g_c[ROWS * NM];
__device__ __nv_bfloat16 g_mb[BATCH * SEQ * SEQ];

// ===========================================================================
// Helpers
// ===========================================================================
__device__ __forceinline__ uint32_t smem_u32(const void* p) {
    uint32_t a;
    asm("{ .reg .u64 t; cvta.to.shared.u64 t, %1; cvt.u32.u64 %0, t; }"
        : "=r"(a) : "l"(p));
    return a;
}
__device__ __forceinline__ void cp16(uint32_t dst, const void* src) {
    asm volatile("cp.async.cg.shared.global [%0], [%1], 16;"
                 :: "r"(dst), "l"(src));
}
__device__ __forceinline__ void cp_commit() {
    asm volatile("cp.async.commit_group;");
}
template<int N> __device__ __forceinline__ void cp_wait() {
    asm volatile("cp.async.wait_group %0;" :: "n"(N));
}
__device__ __forceinline__ void ldm_x4(uint32_t* r, uint32_t a) {
    asm volatile("ldmatrix.sync.aligned.m8n8.x4.shared.b16 {%0,%1,%2,%3}, [%4];"
                 : "=r"(r[0]), "=r"(r[1]), "=r"(r[2]), "=r"(r[3]) : "r"(a));
}
__device__ __forceinline__ void ldm_x4t(uint32_t* r, uint32_t a) {
    asm volatile("ldmatrix.sync.aligned.m8n8.x4.trans.shared.b16 {%0,%1,%2,%3}, [%4];"
                 : "=r"(r[0]), "=r"(r[1]), "=r"(r[2]), "=r"(r[3]) : "r"(a));
}
__device__ __forceinline__ void mma_f16(float* c, const uint32_t* a,
                                        const uint32_t* b) {
    asm volatile(
        "mma.sync.aligned.m16n8k16.row.col.f32.f16.f16.f32 "
        "{%0,%1,%2,%3}, {%4,%5,%6,%7}, {%8,%9}, {%0,%1,%2,%3};"
        : "+f"(c[0]), "+f"(c[1]), "+f"(c[2]), "+f"(c[3])
        : "r"(a[0]), "r"(a[1]), "r"(a[2]), "r"(a[3]), "r"(b[0]), "r"(b[1]));
}
__device__ __forceinline__ uint32_t packh2(float x, float y) {
    __half2 h = __floats2half2_rn(x, y);
    return reinterpret_cast<uint32_t&>(h);
}

// ===========================================================================
// Fused conversion kernel — grid (4096, 3): y=0 x, y=1 weights, y=2 mask
// ===========================================================================
__global__ void conv_all(const float* __restrict__ x,
                         const float* __restrict__ w0, const float* __restrict__ w1,
                         const float* __restrict__ w2, const float* __restrict__ w3,
                         const int* __restrict__ m,
                         __half* __restrict__ xp, __half* __restrict__ wp,
                         __nv_bfloat16* __restrict__ mb)
{
    int i = (blockIdx.x * 256 + threadIdx.x) * 4;
    int y = blockIdx.y;
    if (y == 0) {
        float4 a = *(const float4*)(x + i);
        uint2 o;
        o.x = packh2(a.x, a.y);
        o.y = packh2(a.z, a.w);
        *(uint2*)(xp + i) = o;
    } else if (y == 1) {
        int wsel = i >> 20;
        int wi   = i & ((1 << 20) - 1);
        const float* src = (wsel == 0) ? w0 : (wsel == 1) ? w1
                         : (wsel == 2) ? w2 : w3;
        float4 a = *(const float4*)(src + wi);
        uint2 o;
        o.x = packh2(a.x, a.y);
        o.y = packh2(a.z, a.w);
        *(uint2*)(wp + i) = o;
    } else {
        int4 a = *(const int4*)(m + i);
        __nv_bfloat162 p0 = __floats2bfloat162_rn((float)(a.x - 1) * 1e9f,
                                                  (float)(a.y - 1) * 1e9f);
        __nv_bfloat162 p1 = __floats2bfloat162_rn((float)(a.z - 1) * 1e9f,
                                                  (float)(a.w - 1) * 1e9f);
        uint2 o;
        o.x = reinterpret_cast<uint32_t&>(p0);
        o.y = reinterpret_cast<uint32_t&>(p1);
        *(uint2*)(mb + i) = o;
    }
}

// ===========================================================================
// fp16 GEMM core v3: CTA 128x128, BK=64, 3-stage cp.async ring,
// 512 threads / 16 warps, warp tile 32x32 (2x4 m16n8k16). High occupancy.
// ===========================================================================
#define BKP 72                     // padded K stride (fp16 elems), 144 B
#define ASZH (128 * BKP * 2)       // 18432 bytes per array
#define SSTG (2 * ASZH)            // 36864 per stage
#define GSMEM (3 * SSTG)           // 110592 (2 CTAs/SM)

__device__ __forceinline__ void gemm_core(
    const __half* __restrict__ A_g, const __half* __restrict__ B_g,
    uint32_t sb, int tid, float acc[2][4][4])
{
    const int lane = tid & 31;
    const int wid  = tid >> 5;            // 0..15
    const int wm   = (wid >> 2) * 32;     // 4 row groups of 32
    const int wn   = (wid & 3) * 32;      // 4 col groups of 32

    const __half* gsrc[2] = { A_g, B_g };

    const uint32_t a_off  = ((wm + (lane & 15)) * BKP + (lane >> 4) * 8) * 2;
    const uint32_t b_off4 = ((wn + (lane & 7) + ((lane >> 4) & 1) * 8) * BKP
                             + ((lane >> 3) & 1) * 8) * 2;

#pragma unroll
    for (int i = 0; i < 2; i++)
#pragma unroll
        for (int j = 0; j < 4; j++)
#pragma unroll
            for (int r = 0; r < 4; r++) acc[i][j][r] = 0.0f;

#define GLOAD(stg, kc) do {                                                  \
    uint32_t _sbase = sb + (stg) * SSTG;                                     \
    _Pragma("unroll")                                                        \
    for (int j = 0; j < 4; j++) {                                            \
        int arr = j >> 1;                                                    \
        int w   = tid + (j & 1) * 512;                                       \
        int row = w >> 3;                                                    \
        int c8  = (w & 7) * 8;                                               \
        cp16(_sbase + arr * ASZH + (uint32_t)(row * BKP + c8) * 2,           \
             gsrc[arr] + (size_t)row * 1024 + (kc) + c8);                    \
    } } while (0)

    GLOAD(0, 0);
    cp_commit();
    GLOAD(1, 64);
    cp_commit();

    int s_cur = 0, s_nxt = 2;
    for (int kc = 0; kc < 16; kc++) {
        if (kc < 15) cp_wait<1>(); else cp_wait<0>();
        __syncthreads();
        if (kc < 14) {
            GLOAD(s_nxt, (kc + 2) * 64);
            cp_commit();
        }

        const uint32_t sA = sb + s_cur * SSTG;
        const uint32_t sB = sA + ASZH;

#pragma unroll
        for (int ks = 0; ks < 4; ks++) {
            const uint32_t kb = ks * 32;

            uint32_t af[2][4];
#pragma unroll
            for (int tm = 0; tm < 2; tm++)
                ldm_x4(af[tm], sA + a_off + kb + tm * (16 * BKP * 2));

            uint32_t bfr[2][4];
#pragma unroll
            for (int p = 0; p < 2; p++)
                ldm_x4(bfr[p], sB + b_off4 + kb + p * (16 * BKP * 2));

#pragma unroll
            for (int tm = 0; tm < 2; tm++)
#pragma unroll
                for (int p = 0; p < 2; p++) {
                    mma_f16(acc[tm][2*p],   af[tm], &bfr[p][0]);
                    mma_f16(acc[tm][2*p+1], af[tm], &bfr[p][2]);
                }
        }
        s_cur = (s_cur == 2) ? 0 : s_cur + 1;
        s_nxt = (s_nxt == 2) ? 0 : s_nxt + 1;
    }
#undef GLOAD
}

// ---- fused QKV projection: grid (8, 32, 3), 512 threads ----
__global__ __launch_bounds__(512, 2)
void gemm_qkv(const __half* __restrict__ X, const __half* __restrict__ W,
              const float* __restrict__ bq, const float* __restrict__ bk,
              const float* __restrict__ bv,
              __half* __restrict__ Q, __half* __restrict__ K,
              __half* __restrict__ V)
{
    extern __shared__ __align__(16) char smg[];
    const uint32_t sb = smem_u32(smg);
    const int tid = threadIdx.x;
    const int m0  = blockIdx.y * 128;
    const int n0  = blockIdx.x * 128;
    const int z   = blockIdx.z;

    const __half* Wz   = W + (size_t)z * NM * NM;
    const float*  bias = (z == 0) ? bq : (z == 1) ? bk : bv;
    __half*       Out  = (z == 0) ? Q  : (z == 1) ? K  : V;

    float acc[2][4][4];
    gemm_core(X + (size_t)m0 * 1024, Wz + (size_t)n0 * 1024, sb, tid, acc);

    const int lane = tid & 31;
    const int wid  = tid >> 5;
    const int wm   = (wid >> 2) * 32;
    const int wn   = (wid & 3) * 32;
    const int qr   = lane >> 2;
    const int qc   = (lane & 3) * 2;
#pragma unroll
    for (int tm = 0; tm < 2; tm++) {
        int row = m0 + wm + tm * 16 + qr;
#pragma unroll
        for (int tn = 0; tn < 4; tn++) {
            int col = n0 + wn + tn * 8 + qc;
            float b0 = bias[col], b1 = bias[col + 1];
            *(uint32_t*)(Out + (size_t)row * 1024 + col) =
                packh2(acc[tm][tn][0] + b0, acc[tm][tn][1] + b1);
            *(uint32_t*)(Out + (size_t)(row + 8) * 1024 + col) =
                packh2(acc[tm][tn][2] + b0, acc[tm][tn][3] + b1);
        }
    }
}

// ---- output projection (fp32 out), 512 threads ----
__global__ __launch_bounds__(512, 2)
void gemm_o(const __half* __restrict__ A_g, const __half* __restrict__ B_g,
            const float* __restrict__ bias, float* __restrict__ Cf)
{
    extern __shared__ __align__(16) char smg[];
    const uint32_t sb = smem_u32(smg);
    const int tid = threadIdx.x;
    const int m0  = blockIdx.y * 128;
    const int n0  = blockIdx.x * 128;

    float acc[2][4][4];
    gemm_core(A_g + (size_t)m0 * 1024, B_g + (size_t)n0 * 1024, sb, tid, acc);

    const int lane = tid & 31;
    const int wid  = tid >> 5;
    const int wm   = (wid >> 2) * 32;
    const int wn   = (wid & 3) * 32;
    const int qr   = lane >> 2;
    const int qc   = (lane & 3) * 2;
#pragma unroll
    for (int tm = 0; tm < 2; tm++) {
        int row = m0 + wm + tm * 16 + qr;
#pragma unroll
        for (int tn = 0; tn < 4; tn++) {
            int col = n0 + wn + tn * 8 + qc;
            float b0 = bias[col], b1 = bias[col + 1];
            *(float2*)(Cf + (size_t)row * 1024 + col) =
                make_float2(acc[tm][tn][0] + b0, acc[tm][tn][1] + b1);
            *(float2*)(Cf + (size_t)(row + 8) * 1024 + col) =
                make_float2(acc[tm][tn][2] + b0, acc[tm][tn][3] + b1);
        }
    }
}

// ===========================================================================
// fp16 flash attention with double-buffered K/V (unchanged from R9)
// ===========================================================================
#define ALD 72
#define ABUF (128 * ALD * 2)   // 18432 bytes per buffer

__global__ __launch_bounds__(256)
void attn_h(const __half* __restrict__ q, const __half* __restrict__ k,
            const __half* __restrict__ v, const __nv_bfloat16* __restrict__ mb,
            __half* __restrict__ ctx)
{
    extern __shared__ __align__(16) char sma[];
    const uint32_t sQ  = smem_u32(sma);
    const uint32_t sK0 = sQ + ABUF;
    const uint32_t sV0 = sQ + 2 * ABUF;
    const uint32_t sK1 = sQ + 3 * ABUF;
    const uint32_t sV1 = sQ + 4 * ABUF;

    const int tid  = threadIdx.x;
    const int lane = tid & 31;
    const int wid  = tid >> 5;
    const int q0   = blockIdx.x * 128;
    const int h    = blockIdx.y;
    const int b    = blockIdx.z;

    const size_t base  = (size_t)b * SEQ * NM + (size_t)h * ND;
    const size_t mbase = (size_t)b * SEQ * SEQ;

    const __half* ksrc = k + base;
    const __half* vsrc = v + base;

#define KVLOAD(kbuf, vbuf, k0) do {                                          \
    _Pragma("unroll")                                                        \
    for (int j = 0; j < 8; j++) {                                            \
        int arr = j >> 2;                                                    \
        int w   = tid + (j & 3) * 256;                                       \
        int row = w >> 3;                                                    \
        int c8  = (w & 7) * 8;                                               \
        cp16((arr ? (vbuf) : (kbuf)) + (uint32_t)(row * ALD + c8) * 2,       \
             (arr ? vsrc : ksrc) + (size_t)((k0) + row) * 1024 + c8);        \
    }                                                                        \
    cp_commit(); } while (0)

#pragma unroll
    for (int j = 0; j < 4; j++) {
        int w   = tid + j * 256;
        int row = w >> 3;
        int c8  = (w & 7) * 8;
        cp16(sQ + (uint32_t)(row * ALD + c8) * 2,
             q + base + (size_t)(q0 + row) * 1024 + c8);
    }
    cp_commit();
    KVLOAD(sK0, sV0, 0);

    cp_wait<1>();
    __syncthreads();

    uint32_t qf[4][4];
    {
        uint32_t qo = ((wid * 16 + (lane & 15)) * ALD + (lane >> 4) * 8) * 2;
#pragma unroll
        for (int ks = 0; ks < 4; ks++)
            ldm_x4(qf[ks], sQ + qo + ks * 32);
    }

    float oacc[8][4];
#pragma unroll
    for (int i = 0; i < 8; i++)
#pragma unroll
        for (int r = 0; r < 4; r++) oacc[i][r] = 0.0f;
    float mr1 = -INFINITY, mr2 = -INFINITY, lr1 = 0.0f, lr2 = 0.0f;

    const float SCALE = 0.03125f;
    const int r1 = wid * 16 + (lane >> 2);

    const uint32_t koff = ((lane & 7) * ALD + ((lane >> 3) & 3) * 8) * 2;
    const uint32_t voff = (((lane & 7) + 8 * ((lane >> 3) & 1)) * ALD) * 2
                        + ((lane >> 4) & 1) * 16;

    for (int t = 0; t < 8; t++) {
        cp_wait<0>();
        __syncthreads();

        const uint32_t sK = (t & 1) ? sK1 : sK0;
        const uint32_t sV = (t & 1) ? sV1 : sV0;
        if (t < 7) {
            if (t & 1) KVLOAD(sK0, sV0, (t + 1) * 128);
            else       KVLOAD(sK1, sV1, (t + 1) * 128);
        }
        const int k0 = t * 128;

        float sacc[16][4];
#pragma unroll
        for (int j = 0; j < 16; j++) {
#pragma unroll
            for (int r = 0; r < 4; r++) sacc[j][r] = 0.0f;
            uint32_t ka = koff + (uint32_t)(j * 8 * ALD * 2);
            uint32_t kf[8];
            ldm_x4(kf,     sK + ka);
            ldm_x4(kf + 4, sK + ka + 64);
#pragma unroll
            for (int ks = 0; ks < 4; ks++)
                mma_f16(sacc[j], qf[ks], &kf[ks * 2]);
        }

        const __nv_bfloat16* mp =
            mb + mbase + (size_t)(q0 + r1) * SEQ + k0 + (lane & 3) * 2;
        float rmax1 = -INFINITY, rmax2 = -INFINITY;
#pragma unroll
        for (int j = 0; j < 16; j++) {
            uint32_t ma = *(const uint32_t*)(mp + j * 8);
            uint32_t mc = *(const uint32_t*)(mp + 8 * SEQ + j * 8);
            float2 f1 = __bfloat1622float2(reinterpret_cast<__nv_bfloat162&>(ma));
            float2 f2 = __bfloat1622float2(reinterpret_cast<__nv_bfloat162&>(mc));
            sacc[j][0] = sacc[j][0] * SCALE + f1.x;
            sacc[j][1] = sacc[j][1] * SCALE + f1.y;
            sacc[j][2] = sacc[j][2] * SCALE + f2.x;
            sacc[j][3] = sacc[j][3] * SCALE + f2.y;
            rmax1 = fmaxf(rmax1, fmaxf(sacc[j][0], sacc[j][1]));
            rmax2 = fmaxf(rmax2, fmaxf(sacc[j][2], sacc[j][3]));
        }
#pragma unroll
        for (int off = 1; off < 4; off <<= 1) {
            rmax1 = fmaxf(rmax1, __shfl_xor_sync(0xffffffffu, rmax1, off));
            rmax2 = fmaxf(rmax2, __shfl_xor_sync(0xffffffffu, rmax2, off));
        }

        float mn1 = fmaxf(mr1, rmax1);
        float mn2 = fmaxf(mr2, rmax2);
        float c1 = __expf(mr1 - mn1);
        float c2 = __expf(mr2 - mn2);
        mr1 = mn1; mr2 = mn2;
#pragma unroll
        for (int i = 0; i < 8; i++) {
            oacc[i][0] *= c1; oacc[i][1] *= c1;
            oacc[i][2] *= c2; oacc[i][3] *= c2;
        }
        float rs1 = 0.0f, rs2 = 0.0f;
#pragma unroll
        for (int j = 0; j < 16; j++) {
            sacc[j][0] = __expf(sacc[j][0] - mn1);
            sacc[j][1] = __expf(sacc[j][1] - mn1);
            sacc[j][2] = __expf(sacc[j][2] - mn2);
            sacc[j][3] = __expf(sacc[j][3] - mn2);
            rs1 += sacc[j][0] + sacc[j][1];
            rs2 += sacc[j][2] + sacc[j][3];
        }
#pragma unroll
        for (int off = 1; off < 4; off <<= 1) {
            rs1 += __shfl_xor_sync(0xffffffffu, rs1, off);
            rs2 += __shfl_xor_sync(0xffffffffu, rs2, off);
        }
        lr1 = lr1 * c1 + rs1;
        lr2 = lr2 * c2 + rs2;

#pragma unroll
        for (int ks = 0; ks < 8; ks++) {
            uint32_t ph[4];
            ph[0] = packh2(sacc[2*ks][0],   sacc[2*ks][1]);
            ph[1] = packh2(sacc[2*ks][2],   sacc[2*ks][3]);
            ph[2] = packh2(sacc[2*ks+1][0], sacc[2*ks+1][1]);
            ph[3] = packh2(sacc[2*ks+1][2], sacc[2*ks+1][3]);

            uint32_t va = voff + (uint32_t)(ks * 16 * ALD * 2);
#pragma unroll
            for (int tp = 0; tp < 4; tp++) {
                uint32_t vf[4];
                ldm_x4t(vf, sV + va + tp * 32);
                mma_f16(oacc[2*tp],   ph, &vf[0]);
                mma_f16(oacc[2*tp+1], ph, &vf[2]);
            }
        }
    }
#undef KVLOAD

    float i1 = 1.0f / lr1, i2 = 1.0f / lr2;
    size_t off0 = base + (size_t)(q0 + r1) * NM + (lane & 3) * 2;
#pragma unroll
    for (int tn = 0; tn < 8; tn++) {
        *(uint32_t*)(ctx + off0 + tn * 8) =
            packh2(oacc[tn][0] * i1, oacc[tn][1] * i1);
        *(uint32_t*)(ctx + off0 + 8 * NM + tn * 8) =
            packh2(oacc[tn][2] * i2, oacc[tn][3] * i2);
    }
}

// ---------------------------------------------------------------------------
// kernel_launch — inputs: x, mask, Wq, bq, Wk, bk, Wv, bv, Wo, bo
// ---------------------------------------------------------------------------
extern "C" void kernel_launch(void* const* d_in, const int* in_sizes, int n_in,
                              void* d_out, int out_size)
{
    const float* x    = (const float*)d_in[0];
    const int*   mask = (const int*)  d_in[1];
    const float* Wq   = (const float*)d_in[2];
    const float* bq   = (const float*)d_in[3];
    const float* Wk   = (const float*)d_in[4];
    const float* bk   = (const float*)d_in[5];
    const float* Wv   = (const float*)d_in[6];
    const float* bv   = (const float*)d_in[7];
    const float* Wo   = (const float*)d_in[8];
    const float* bo   = (const float*)d_in[9];
    float* out = (float*)d_out;

    __half *xp, *wp, *qp, *kp, *vp, *cp;
    __nv_bfloat16* mbp;
    cudaGetSymbolAddress((void**)&xp, g_x);
    cudaGetSymbolAddress((void**)&wp, g_w);
    cudaGetSymbolAddress((void**)&qp, g_q);
    cudaGetSymbolAddress((void**)&kp, g_k);
    cudaGetSymbolAddress((void**)&vp, g_v);
    cudaGetSymbolAddress((void**)&cp, g_c);
    cudaGetSymbolAddress((void**)&mbp, g_mb);

    // ---- conversions (one launch) ----
    dim3 cgrid(ROWS * NM / 1024, 3);
    conv_all<<<cgrid, 256>>>(x, Wq, Wk, Wv, Wo, mask, xp, wp, mbp);

    // ---- fused QKV projection ----
    cudaFuncSetAttribute(gemm_qkv,
                         cudaFuncAttributeMaxDynamicSharedMemorySize, GSMEM);
    cudaFuncSetAttribute(gemm_o,
                         cudaFuncAttributeMaxDynamicSharedMemorySize, GSMEM);
    dim3 gblock(512);
    dim3 qgrid(NM / 128, ROWS / 128, 3);   // (8, 32, 3)
    gemm_qkv<<<qgrid, gblock, GSMEM>>>(xp, wp, bq, bk, bv, qp, kp, vp);

    // ---- attention ----
    const int asmem = 5 * ABUF;   // 92160
    cudaFuncSetAttribute(attn_h,
                         cudaFuncAttributeMaxDynamicSharedMemorySize, asmem);
    dim3 agrid(SEQ / 128, NH, BATCH);
    attn_h<<<agrid, 256, asmem>>>(qp, kp, vp, mbp, cp);

    // ---- output projection ----
    dim3 ogrid(NM / 128, ROWS / 128);
    gemm_o<<<ogrid, gblock, GSMEM>>>(cp, wp + 3 * (size_t)NM * NM, bo, out);
}

// round 12
// speedup vs baseline: 1.1283x; 1.1283x over previous
#include <cuda_runtime.h>
#include <cuda_bf16.h>
#include <cuda_fp16.h>
#include <math.h>
#include <stdint.h>

// Problem constants
#define NM 1024
#define NH 16
#define ND 64
#define BATCH 4
#define SEQ 1024
#define ROWS (BATCH*SEQ)   // 4096

// ---------------------------------------------------------------------------
// Scratch (device globals; no allocation allowed)
// ---------------------------------------------------------------------------
__device__ __half g_x[ROWS * NM];
__device__ __half g_w[4][NM * NM];
__device__ __half g_q[ROWS * NM];
__device__ __half g_k[ROWS * NM];
__device__ __half g_v[ROWS * NM];
__device__ __half g_c[ROWS * NM];
__device__ __nv_bfloat16 g_mb[BATCH * SEQ * SEQ];

// ===========================================================================
// Helpers
// ===========================================================================
__device__ __forceinline__ uint32_t smem_u32(const void* p) {
    uint32_t a;
    asm("{ .reg .u64 t; cvta.to.shared.u64 t, %1; cvt.u32.u64 %0, t; }"
        : "=r"(a) : "l"(p));
    return a;
}
__device__ __forceinline__ void cp16(uint32_t dst, const void* src) {
    asm volatile("cp.async.cg.shared.global [%0], [%1], 16;"
                 :: "r"(dst), "l"(src));
}
__device__ __forceinline__ void cp_commit() {
    asm volatile("cp.async.commit_group;");
}
template<int N> __device__ __forceinline__ void cp_wait() {
    asm volatile("cp.async.wait_group %0;" :: "n"(N));
}
__device__ __forceinline__ void ldm_x4(uint32_t* r, uint32_t a) {
    asm volatile("ldmatrix.sync.aligned.m8n8.x4.shared.b16 {%0,%1,%2,%3}, [%4];"
                 : "=r"(r[0]), "=r"(r[1]), "=r"(r[2]), "=r"(r[3]) : "r"(a));
}
__device__ __forceinline__ void ldm_x4t(uint32_t* r, uint32_t a) {
    asm volatile("ldmatrix.sync.aligned.m8n8.x4.trans.shared.b16 {%0,%1,%2,%3}, [%4];"
                 : "=r"(r[0]), "=r"(r[1]), "=r"(r[2]), "=r"(r[3]) : "r"(a));
}
__device__ __forceinline__ void mma_f16(float* c, const uint32_t* a,
                                        const uint32_t* b) {
    asm volatile(
        "mma.sync.aligned.m16n8k16.row.col.f32.f16.f16.f32 "
        "{%0,%1,%2,%3}, {%4,%5,%6,%7}, {%8,%9}, {%0,%1,%2,%3};"
        : "+f"(c[0]), "+f"(c[1]), "+f"(c[2]), "+f"(c[3])
        : "r"(a[0]), "r"(a[1]), "r"(a[2]), "r"(a[3]), "r"(b[0]), "r"(b[1]));
}
__device__ __forceinline__ uint32_t packh2(float x, float y) {
    __half2 h = __floats2half2_rn(x, y);
    return reinterpret_cast<uint32_t&>(h);
}

// ===========================================================================
// Fused conversion kernel — grid (4096, 3): y=0 x, y=1 weights, y=2 mask
// ===========================================================================
__global__ void conv_all(const float* __restrict__ x,
                         const float* __restrict__ w0, const float* __restrict__ w1,
                         const float* __restrict__ w2, const float* __restrict__ w3,
                         const int* __restrict__ m,
                         __half* __restrict__ xp, __half* __restrict__ wp,
                         __nv_bfloat16* __restrict__ mb)
{
    int i = (blockIdx.x * 256 + threadIdx.x) * 4;
    int y = blockIdx.y;
    if (y == 0) {
        float4 a = *(const float4*)(x + i);
        uint2 o;
        o.x = packh2(a.x, a.y);
        o.y = packh2(a.z, a.w);
        *(uint2*)(xp + i) = o;
    } else if (y == 1) {
        int wsel = i >> 20;
        int wi   = i & ((1 << 20) - 1);
        const float* src = (wsel == 0) ? w0 : (wsel == 1) ? w1
                         : (wsel == 2) ? w2 : w3;
        float4 a = *(const float4*)(src + wi);
        uint2 o;
        o.x = packh2(a.x, a.y);
        o.y = packh2(a.z, a.w);
        *(uint2*)(wp + i) = o;
    } else {
        int4 a = *(const int4*)(m + i);
        __nv_bfloat162 p0 = __floats2bfloat162_rn((float)(a.x - 1) * 1e9f,
                                                  (float)(a.y - 1) * 1e9f);
        __nv_bfloat162 p1 = __floats2bfloat162_rn((float)(a.z - 1) * 1e9f,
                                                  (float)(a.w - 1) * 1e9f);
        uint2 o;
        o.x = reinterpret_cast<uint32_t&>(p0);
        o.y = reinterpret_cast<uint32_t&>(p1);
        *(uint2*)(mb + i) = o;
    }
}

// ===========================================================================
// fp16 GEMM core (R9 version: CTA 128x128, BK=64, 3-stage ring, 256 thr)
// ===========================================================================
#define BKP 72                     // padded K stride (fp16 elems), 144 B
#define ASZH (128 * BKP * 2)       // 18432 bytes per array
#define SSTG (2 * ASZH)            // 36864 per stage
#define GSMEM (3 * SSTG)           // 110592

__device__ __forceinline__ void gemm_core(
    const __half* __restrict__ A_g, const __half* __restrict__ B_g,
    uint32_t sb, int tid, float acc[4][4][4])
{
    const int lane = tid & 31;
    const int wid  = tid >> 5;
    const int wm   = (wid >> 2) * 64;
    const int wn   = (wid & 3) * 32;

    const __half* gsrc[2] = { A_g, B_g };

    const uint32_t a_off  = ((wm + (lane & 15)) * BKP + (lane >> 4) * 8) * 2;
    const uint32_t b_off4 = ((wn + (lane & 7) + ((lane >> 4) & 1) * 8) * BKP
                             + ((lane >> 3) & 1) * 8) * 2;

#pragma unroll
    for (int i = 0; i < 4; i++)
#pragma unroll
        for (int j = 0; j < 4; j++)
#pragma unroll
            for (int r = 0; r < 4; r++) acc[i][j][r] = 0.0f;

#define GLOAD(stg, kc) do {                                                  \
    uint32_t _sbase = sb + (stg) * SSTG;                                     \
    _Pragma("unroll")                                                        \
    for (int j = 0; j < 8; j++) {                                            \
        int arr = j >> 2;                                                    \
        int w   = tid + (j & 3) * 256;                                       \
        int row = w >> 3;                                                    \
        int c8  = (w & 7) * 8;                                               \
        cp16(_sbase + arr * ASZH + (uint32_t)(row * BKP + c8) * 2,           \
             gsrc[arr] + (size_t)row * 1024 + (kc) + c8);                    \
    } } while (0)

    GLOAD(0, 0);
    cp_commit();
    GLOAD(1, 64);
    cp_commit();

    int s_cur = 0, s_nxt = 2;
    for (int kc = 0; kc < 16; kc++) {
        if (kc < 15) cp_wait<1>(); else cp_wait<0>();
        __syncthreads();
        if (kc < 14) {
            GLOAD(s_nxt, (kc + 2) * 64);
            cp_commit();
        }

        const uint32_t sA = sb + s_cur * SSTG;
        const uint32_t sB = sA + ASZH;

#pragma unroll
        for (int ks = 0; ks < 4; ks++) {
            const uint32_t kb = ks * 32;

            uint32_t af[4][4];
#pragma unroll
            for (int tm = 0; tm < 4; tm++)
                ldm_x4(af[tm], sA + a_off + kb + tm * (16 * BKP * 2));

            uint32_t bfr[2][4];
#pragma unroll
            for (int p = 0; p < 2; p++)
                ldm_x4(bfr[p], sB + b_off4 + kb + p * (16 * BKP * 2));

#pragma unroll
            for (int tm = 0; tm < 4; tm++)
#pragma unroll
                for (int p = 0; p < 2; p++) {
                    mma_f16(acc[tm][2*p],   af[tm], &bfr[p][0]);
                    mma_f16(acc[tm][2*p+1], af[tm], &bfr[p][2]);
                }
        }
        s_cur = (s_cur == 2) ? 0 : s_cur + 1;
        s_nxt = (s_nxt == 2) ? 0 : s_nxt + 1;
    }
#undef GLOAD
}

// ---- fused QKV projection: grid (8, 32, 3) ----
__global__ __launch_bounds__(256, 2)
void gemm_qkv(const __half* __restrict__ X, const __half* __restrict__ W,
              const float* __restrict__ bq, const float* __restrict__ bk,
              const float* __restrict__ bv,
              __half* __restrict__ Q, __half* __restrict__ K,
              __half* __restrict__ V)
{
    extern __shared__ __align__(16) char smg[];
    const uint32_t sb = smem_u32(smg);
    const int tid = threadIdx.x;
    const int m0  = blockIdx.y * 128;
    const int n0  = blockIdx.x * 128;
    const int z   = blockIdx.z;

    const __half* Wz   = W + (size_t)z * NM * NM;
    const float*  bias = (z == 0) ? bq : (z == 1) ? bk : bv;
    __half*       Out  = (z == 0) ? Q  : (z == 1) ? K  : V;

    float acc[4][4][4];
    gemm_core(X + (size_t)m0 * 1024, Wz + (size_t)n0 * 1024, sb, tid, acc);

    const int lane = tid & 31;
    const int wid  = tid >> 5;
    const int wm   = (wid >> 2) * 64;
    const int wn   = (wid & 3) * 32;
    const int qr   = lane >> 2;
    const int qc   = (lane & 3) * 2;
#pragma unroll
    for (int tm = 0; tm < 4; tm++) {
        int row = m0 + wm + tm * 16 + qr;
#pragma unroll
        for (int tn = 0; tn < 4; tn++) {
            int col = n0 + wn + tn * 8 + qc;
            float b0 = bias[col], b1 = bias[col + 1];
            *(uint32_t*)(Out + (size_t)row * 1024 + col) =
                packh2(acc[tm][tn][0] + b0, acc[tm][tn][1] + b1);
            *(uint32_t*)(Out + (size_t)(row + 8) * 1024 + col) =
                packh2(acc[tm][tn][2] + b0, acc[tm][tn][3] + b1);
        }
    }
}

// ---- output projection (fp32 out) ----
__global__ __launch_bounds__(256, 2)
void gemm_o(const __half* __restrict__ A_g, const __half* __restrict__ B_g,
            const float* __restrict__ bias, float* __restrict__ Cf)
{
    extern __shared__ __align__(16) char smg[];
    const uint32_t sb = smem_u32(smg);
    const int tid = threadIdx.x;
    const int m0  = blockIdx.y * 128;
    const int n0  = blockIdx.x * 128;

    float acc[4][4][4];
    gemm_core(A_g + (size_t)m0 * 1024, B_g + (size_t)n0 * 1024, sb, tid, acc);

    const int lane = tid & 31;
    const int wid  = tid >> 5;
    const int wm   = (wid >> 2) * 64;
    const int wn   = (wid & 3) * 32;
    const int qr   = lane >> 2;
    const int qc   = (lane & 3) * 2;
#pragma unroll
    for (int tm = 0; tm < 4; tm++) {
        int row = m0 + wm + tm * 16 + qr;
#pragma unroll
        for (int tn = 0; tn < 4; tn++) {
            int col = n0 + wn + tn * 8 + qc;
            float b0 = bias[col], b1 = bias[col + 1];
            *(float2*)(Cf + (size_t)row * 1024 + col) =
                make_float2(acc[tm][tn][0] + b0, acc[tm][tn][1] + b1);
            *(float2*)(Cf + (size_t)(row + 8) * 1024 + col) =
                make_float2(acc[tm][tn][2] + b0, acc[tm][tn][3] + b1);
        }
    }
}

// ===========================================================================
// fp16 flash attention v3: no-max softmax (scores are O(1); exp directly,
// masked -> exp(-1e9)=0), P packed to fp16 on the fly, occupancy 2.
// CTA: 128 q-rows x one head, 8 warps, double-buffered K/V.
// ===========================================================================
#define ALD 72
#define ABUF (128 * ALD * 2)   // 18432 bytes per buffer

__global__ __launch_bounds__(256, 2)
void attn_h(const __half* __restrict__ q, const __half* __restrict__ k,
            const __half* __restrict__ v, const __nv_bfloat16* __restrict__ mb,
            __half* __restrict__ ctx)
{
    extern __shared__ __align__(16) char sma[];
    const uint32_t sQ  = smem_u32(sma);
    const uint32_t sK0 = sQ + ABUF;
    const uint32_t sV0 = sQ + 2 * ABUF;
    const uint32_t sK1 = sQ + 3 * ABUF;
    const uint32_t sV1 = sQ + 4 * ABUF;

    const int tid  = threadIdx.x;
    const int lane = tid & 31;
    const int wid  = tid >> 5;
    const int q0   = blockIdx.x * 128;
    const int h    = blockIdx.y;
    const int b    = blockIdx.z;

    const size_t base  = (size_t)b * SEQ * NM + (size_t)h * ND;
    const size_t mbase = (size_t)b * SEQ * SEQ;

    const __half* ksrc = k + base;
    const __half* vsrc = v + base;

#define KVLOAD(kbuf, vbuf, k0) do {                                          \
    _Pragma("unroll")                                                        \
    for (int j = 0; j < 8; j++) {                                            \
        int arr = j >> 2;                                                    \
        int w   = tid + (j & 3) * 256;                                       \
        int row = w >> 3;                                                    \
        int c8  = (w & 7) * 8;                                               \
        cp16((arr ? (vbuf) : (kbuf)) + (uint32_t)(row * ALD + c8) * 2,       \
             (arr ? vsrc : ksrc) + (size_t)((k0) + row) * 1024 + c8);        \
    }                                                                        \
    cp_commit(); } while (0)

#pragma unroll
    for (int j = 0; j < 4; j++) {
        int w   = tid + j * 256;
        int row = w >> 3;
        int c8  = (w & 7) * 8;
        cp16(sQ + (uint32_t)(row * ALD + c8) * 2,
             q + base + (size_t)(q0 + row) * 1024 + c8);
    }
    cp_commit();
    KVLOAD(sK0, sV0, 0);

    cp_wait<1>();
    __syncthreads();

    uint32_t qf[4][4];
    {
        uint32_t qo = ((wid * 16 + (lane & 15)) * ALD + (lane >> 4) * 8) * 2;
#pragma unroll
        for (int ks = 0; ks < 4; ks++)
            ldm_x4(qf[ks], sQ + qo + ks * 32);
    }

    float oacc[8][4];
#pragma unroll
    for (int i = 0; i < 8; i++)
#pragma unroll
        for (int r = 0; r < 4; r++) oacc[i][r] = 0.0f;
    float rs1 = 0.0f, rs2 = 0.0f;   // running row sums (reduced at the end)

    const float SCALE = 0.03125f;
    const int r1 = wid * 16 + (lane >> 2);

    const uint32_t koff = ((lane & 7) * ALD + ((lane >> 3) & 3) * 8) * 2;
    const uint32_t voff = (((lane & 7) + 8 * ((lane >> 3) & 1)) * ALD) * 2
                        + ((lane >> 4) & 1) * 16;

    for (int t = 0; t < 8; t++) {
        cp_wait<0>();
        __syncthreads();

        const uint32_t sK = (t & 1) ? sK1 : sK0;
        const uint32_t sV = (t & 1) ? sV1 : sV0;
        if (t < 7) {
            if (t & 1) KVLOAD(sK0, sV0, (t + 1) * 128);
            else       KVLOAD(sK1, sV1, (t + 1) * 128);
        }
        const int k0 = t * 128;

        // ---- S tile -> exp -> fp16 P fragments (fused, no max pass) ----
        const __nv_bfloat16* mp =
            mb + mbase + (size_t)(q0 + r1) * SEQ + k0 + (lane & 3) * 2;
        uint32_t ph[16][2];
#pragma unroll
        for (int j = 0; j < 16; j++) {
            float s4[4] = {0.0f, 0.0f, 0.0f, 0.0f};
            uint32_t ka = koff + (uint32_t)(j * 8 * ALD * 2);
            uint32_t kf[8];
            ldm_x4(kf,     sK + ka);
            ldm_x4(kf + 4, sK + ka + 64);
#pragma unroll
            for (int ks = 0; ks < 4; ks++)
                mma_f16(s4, qf[ks], &kf[ks * 2]);

            uint32_t ma = *(const uint32_t*)(mp + j * 8);
            uint32_t mc = *(const uint32_t*)(mp + 8 * SEQ + j * 8);
            float2 f1 = __bfloat1622float2(reinterpret_cast<__nv_bfloat162&>(ma));
            float2 f2 = __bfloat1622float2(reinterpret_cast<__nv_bfloat162&>(mc));
            float e0 = __expf(s4[0] * SCALE + f1.x);
            float e1 = __expf(s4[1] * SCALE + f1.y);
            float e2 = __expf(s4[2] * SCALE + f2.x);
            float e3 = __expf(s4[3] * SCALE + f2.y);
            rs1 += e0 + e1;
            rs2 += e2 + e3;
            ph[j][0] = packh2(e0, e1);
            ph[j][1] = packh2(e2, e3);
        }

        // ---- O += P V ----
#pragma unroll
        for (int ks = 0; ks < 8; ks++) {
            uint32_t pa[4] = { ph[2*ks][0], ph[2*ks][1],
                               ph[2*ks+1][0], ph[2*ks+1][1] };
            uint32_t va = voff + (uint32_t)(ks * 16 * ALD * 2);
#pragma unroll
            for (int tp = 0; tp < 4; tp++) {
                uint32_t vf[4];
                ldm_x4t(vf, sV + va + tp * 32);
                mma_f16(oacc[2*tp],   pa, &vf[0]);
                mma_f16(oacc[2*tp+1], pa, &vf[2]);
            }
        }
    }
#undef KVLOAD

    // ---- single final row-sum reduction over the 4-lane quad ----
#pragma unroll
    for (int off = 1; off < 4; off <<= 1) {
        rs1 += __shfl_xor_sync(0xffffffffu, rs1, off);
        rs2 += __shfl_xor_sync(0xffffffffu, rs2, off);
    }

    float i1 = 1.0f / rs1, i2 = 1.0f / rs2;
    size_t off0 = base + (size_t)(q0 + r1) * NM + (lane & 3) * 2;
#pragma unroll
    for (int tn = 0; tn < 8; tn++) {
        *(uint32_t*)(ctx + off0 + tn * 8) =
            packh2(oacc[tn][0] * i1, oacc[tn][1] * i1);
        *(uint32_t*)(ctx + off0 + 8 * NM + tn * 8) =
            packh2(oacc[tn][2] * i2, oacc[tn][3] * i2);
    }
}

// ---------------------------------------------------------------------------
// kernel_launch — inputs: x, mask, Wq, bq, Wk, bk, Wv, bv, Wo, bo
// ---------------------------------------------------------------------------
extern "C" void kernel_launch(void* const* d_in, const int* in_sizes, int n_in,
                              void* d_out, int out_size)
{
    const float* x    = (const float*)d_in[0];
    const int*   mask = (const int*)  d_in[1];
    const float* Wq   = (const float*)d_in[2];
    const float* bq   = (const float*)d_in[3];
    const float* Wk   = (const float*)d_in[4];
    const float* bk   = (const float*)d_in[5];
    const float* Wv   = (const float*)d_in[6];
    const float* bv   = (const float*)d_in[7];
    const float* Wo   = (const float*)d_in[8];
    const float* bo   = (const float*)d_in[9];
    float* out = (float*)d_out;

    __half *xp, *wp, *qp, *kp, *vp, *cp;
    __nv_bfloat16* mbp;
    cudaGetSymbolAddress((void**)&xp, g_x);
    cudaGetSymbolAddress((void**)&wp, g_w);
    cudaGetSymbolAddress((void**)&qp, g_q);
    cudaGetSymbolAddress((void**)&kp, g_k);
    cudaGetSymbolAddress((void**)&vp, g_v);
    cudaGetSymbolAddress((void**)&cp, g_c);
    cudaGetSymbolAddress((void**)&mbp, g_mb);

    // ---- conversions (one launch) ----
    dim3 cgrid(ROWS * NM / 1024, 3);
    conv_all<<<cgrid, 256>>>(x, Wq, Wk, Wv, Wo, mask, xp, wp, mbp);

    // ---- fused QKV projection ----
    cudaFuncSetAttribute(gemm_qkv,
                         cudaFuncAttributeMaxDynamicSharedMemorySize, GSMEM);
    cudaFuncSetAttribute(gemm_o,
                         cudaFuncAttributeMaxDynamicSharedMemorySize, GSMEM);
    dim3 gblock(256);
    dim3 qgrid(NM / 128, ROWS / 128, 3);   // (8, 32, 3)
    gemm_qkv<<<qgrid, gblock, GSMEM>>>(xp, wp, bq, bk, bv, qp, kp, vp);

    // ---- attention ----
    const int asmem = 5 * ABUF;   // 92160
    cudaFuncSetAttribute(attn_h,
                         cudaFuncAttributeMaxDynamicSharedMemorySize, asmem);
    dim3 agrid(SEQ / 128, NH, BATCH);
    attn_h<<<agrid, 256, asmem>>>(qp, kp, vp, mbp, cp);

    // ---- output projection ----
    dim3 ogrid(NM / 128, ROWS / 128);
    gemm_o<<<ogrid, gblock, GSMEM>>>(cp, wp + 3 * (size_t)NM * NM, bo, out);
}